// round 5
// baseline (speedup 1.0000x reference)
#include <cuda_runtime.h>
#include <math.h>

// Problem shape (fixed by the reference)
#define BB 64
#define SS 4096
#define DD 1024
#define SPLIT 16
#define CHUNK (SS / SPLIT)      // 256 rows per CTA
#define THREADS 256
#define NW (THREADS / 32)       // 8 warps; each warp owns whole rows
#define F4 (DD / 4)             // 256 float4 per row
#define JV 8                    // float4 per lane per row (32 lanes * 8 = 256)

// Split-K scratch (allocation-free rule: __device__ globals)
__device__ float g_part_m[BB * SPLIT];
__device__ float g_part_l[BB * SPLIT];
__device__ float4 g_part_acc[BB * SPLIT * F4];

__global__ __launch_bounds__(THREADS)
void pool_partial_kernel(const float* __restrict__ x,
                         const int* __restrict__ mask,
                         const float* __restrict__ w)
{
    const int b     = blockIdx.x;
    const int chunk = blockIdx.y;
    const int s0    = chunk * CHUNK;
    const int tid   = threadIdx.x;
    const int lane  = tid & 31;
    const int warp  = tid >> 5;

    __shared__ unsigned short sh_valid[CHUNK];
    __shared__ int    sh_nvalid;
    __shared__ float4 sh_w[F4];
    __shared__ float  sh_m[NW];
    __shared__ float  sh_l[NW];
    __shared__ float4 sh_acc[NW][F4];

    // stage w into smem (one float4 per thread)
    sh_w[tid] = reinterpret_cast<const float4*>(w)[tid];

    // --- Deterministic mask compaction (warp 0 only) ---
    if (warp == 0) {
        int base = 0;
        const int* mrow = mask + (size_t)b * SS + s0;
        #pragma unroll
        for (int j = 0; j < CHUNK; j += 32) {
            int mv = mrow[j + lane];
            unsigned bal = __ballot_sync(0xffffffffu, mv != 0);
            if (mv != 0) {
                int pos = base + __popc(bal & ((1u << lane) - 1u));
                sh_valid[pos] = (unsigned short)(j + lane);
            }
            base += __popc(bal);
        }
        if (lane == 0) sh_nvalid = base;
    }
    __syncthreads();
    const int nv = sh_nvalid;

    const float4* __restrict__ xb =
        reinterpret_cast<const float4*>(x) + (size_t)b * SS * F4;

    // per-warp online softmax state over rows i = warp, warp+NW, ...
    float  m = -INFINITY;
    float  l = 0.0f;
    float4 acc[JV];
    #pragma unroll
    for (int j = 0; j < JV; j++) acc[j] = make_float4(0.f, 0.f, 0.f, 0.f);

    // depth-1 software pipeline: prefetch row i+NW while reducing row i
    float4 nxt[JV];
    if (warp < nv) {
        const float4* __restrict__ row0 =
            xb + (size_t)(s0 + sh_valid[warp]) * F4;
        #pragma unroll
        for (int j = 0; j < JV; j++) nxt[j] = row0[lane + 32 * j];
    }

    for (int i = warp; i < nv; i += NW) {
        float4 cur[JV];
        #pragma unroll
        for (int j = 0; j < JV; j++) cur[j] = nxt[j];

        // issue next row's 8 LDG.128 before consuming cur
        if (i + NW < nv) {
            const float4* __restrict__ rown =
                xb + (size_t)(s0 + sh_valid[i + NW]) * F4;
            #pragma unroll
            for (int j = 0; j < JV; j++) nxt[j] = rown[lane + 32 * j];
        }

        // dot with w (w from smem, conflict-free)
        float pd = 0.f;
        #pragma unroll
        for (int j = 0; j < JV; j++) {
            float4 wv = sh_w[lane + 32 * j];
            pd += cur[j].x * wv.x + cur[j].y * wv.y
                + cur[j].z * wv.z + cur[j].w * wv.w;
        }
        #pragma unroll
        for (int o = 16; o > 0; o >>= 1)
            pd += __shfl_xor_sync(0xffffffffu, pd, o);

        // online softmax update (no barriers; compacted idx always valid)
        float mn    = fmaxf(m, pd);
        float scale = __expf(m - mn);     // first row: exp(-inf)=0
        float pc    = __expf(pd - mn);
        l = l * scale + pc;
        #pragma unroll
        for (int j = 0; j < JV; j++) {
            acc[j].x = acc[j].x * scale + pc * cur[j].x;
            acc[j].y = acc[j].y * scale + pc * cur[j].y;
            acc[j].z = acc[j].z * scale + pc * cur[j].z;
            acc[j].w = acc[j].w * scale + pc * cur[j].w;
        }
        m = mn;
    }

    // --- merge 8 warp-partials via smem (one barrier total) ---
    if (lane == 0) { sh_m[warp] = m; sh_l[warp] = l; }
    #pragma unroll
    for (int j = 0; j < JV; j++) sh_acc[warp][lane + 32 * j] = acc[j];
    __syncthreads();

    float M = -INFINITY;
    #pragma unroll
    for (int wI = 0; wI < NW; wI++) M = fmaxf(M, sh_m[wI]);

    float  L = 0.0f;
    float4 o = make_float4(0.f, 0.f, 0.f, 0.f);
    #pragma unroll
    for (int wI = 0; wI < NW; wI++) {
        float e = __expf(sh_m[wI] - M);   // empty warp: exp(-inf)=0
        L += e * sh_l[wI];
        float4 a = sh_acc[wI][tid];
        o.x += e * a.x; o.y += e * a.y; o.z += e * a.z; o.w += e * a.w;
    }

    const int pidx = b * SPLIT + chunk;
    if (tid == 0) { g_part_m[pidx] = M; g_part_l[pidx] = L; }
    g_part_acc[(size_t)pidx * F4 + tid] = o;
}

#define CSPLIT 4
#define CTHREADS (F4 / CSPLIT)   // 64 threads, one column each

__global__ __launch_bounds__(CTHREADS)
void pool_combine_kernel(float* __restrict__ out)
{
    const int b   = blockIdx.x;
    const int c   = blockIdx.y * CTHREADS + threadIdx.x;

    float M = -INFINITY;
    #pragma unroll
    for (int j = 0; j < SPLIT; j++)
        M = fmaxf(M, g_part_m[b * SPLIT + j]);

    float  L = 0.0f;
    float4 o = make_float4(0.f, 0.f, 0.f, 0.f);
    #pragma unroll
    for (int j = 0; j < SPLIT; j++) {
        const int pidx = b * SPLIT + j;
        float e = __expf(g_part_m[pidx] - M);   // empty chunk: exp(-inf)=0
        L += e * g_part_l[pidx];
        float4 a = g_part_acc[(size_t)pidx * F4 + c];
        o.x += e * a.x; o.y += e * a.y; o.z += e * a.z; o.w += e * a.w;
    }
    float inv = 1.0f / L;
    o.x *= inv; o.y *= inv; o.z *= inv; o.w *= inv;
    reinterpret_cast<float4*>(out)[(size_t)b * F4 + c] = o;
}

extern "C" void kernel_launch(void* const* d_in, const int* in_sizes, int n_in,
                              void* d_out, int out_size)
{
    const float* x    = (const float*)d_in[0];
    const int*   mask = (const int*)d_in[1];
    const float* w    = (const float*)d_in[2];
    float*       out  = (float*)d_out;

    dim3 grid(BB, SPLIT);
    pool_partial_kernel<<<grid, THREADS>>>(x, mask, w);
    pool_combine_kernel<<<dim3(BB, CSPLIT), CTHREADS>>>(out);
}